// round 15
// baseline (speedup 1.0000x reference)
#include <cuda_runtime.h>

#define SDIM 26
#define SS   676          // 26*26
#define CNUM 80
#define NCH  255          // 3*(5+80)
#define NB   32
#define BATCH 256
#define IPB  2            // images per block
#define TPI  512          // threads per image
#define NCTA (BATCH / IPB)
#define DIV  16.0f        // 416/26
#define IMG  416.0f

__device__ float g_partial[NCTA];
__device__ unsigned int g_count = 0;

__device__ __constant__ float c_anchor[9][2] = {
    {10.f,13.f},{16.f,30.f},{33.f,23.f},{30.f,61.f},{62.f,45.f},
    {59.f,119.f},{116.f,90.f},{156.f,198.f},{373.f,326.f}};

__device__ __forceinline__ float warp_sum(float v) {
#pragma unroll
    for (int o = 16; o > 0; o >>= 1) v += __shfl_down_sync(0xffffffffu, v, o);
    return v;
}

__global__ __launch_bounds__(1024) void yolo_fused_kernel(
    const float* __restrict__ x,      // (B, 255, 26, 26)
    const float* __restrict__ box,    // (B, 32, 5)
    const int*   __restrict__ bidx,   // (B, 32)
    float*       __restrict__ out)
{
    const int tid  = threadIdx.x;
    const int half = tid >> 9;            // which image within the block
    const int ltid = tid & (TPI - 1);     // thread id within the half
    const int b    = blockIdx.x * IPB + half;
    const float* xb = x + (size_t)b * NCH * SS;

    __shared__ float sh_wl[IPB][16];      // per-warp label partials
    __shared__ float sh_wn[IPB][16];      // per-warp noobj partials
    __shared__ float sh_scalar[IPB][3];   // boxloss, corr, ucnt
    __shared__ float sh_loss[IPB];
    __shared__ int   sh_islast;

    // ================= issue ALL independent loads up front =================

    // noobj float4 (507 per image, one predicated load per thread)
    float4 nv = make_float4(0.f, 0.f, 0.f, 0.f);
    if (ltid < 3 * (SS / 4)) {
        int c = ltid / (SS / 4);
        int o = ltid - c * (SS / 4);
        nv = ((const float4*)(xb + (size_t)(c * 85) * SS))[o];
    }

    // per-thread gather address: t = box index (16 threads share), jbase = channel lane
    const int t     = ltid >> 4;
    const int jbase = ltid & 15;
    const float* bp = box + ((size_t)b * NB + t) * 5;
    const float  cls = bp[0];
    const float  cx  = bp[1];
    const float  cy  = bp[2];
    const int    ni  = bidx[(size_t)b * NB + t];     // 3..5
    const int    base = (ni - 3) * (5 + CNUM);       // 0 / 85 / 170
    const int    ix  = (int)(cx / DIV);
    const int    iy  = (int)(cy / DIV);
    const int    key = base * SS + ix * SDIM + iy;
    const int    off = key + 5 * SS;

    // 5 independent label loads, issued before any sync
    float lab[5];
#pragma unroll
    for (int k = 0; k < 5; ++k)
        lab[k] = xb[(size_t)(off + (jbase + (k << 4)) * SS)];

    // ================= warp 0 / warp 16: per-box scalar path =================
    if (ltid < NB) {
        // this lane owns box 'ltid' (recompute; data is L1-hot)
        const float* bpl = box + ((size_t)b * NB + ltid) * 5;
        float cxl = bpl[1];
        float cyl = bpl[2];
        float w   = bpl[3];
        float h   = bpl[4];
        int   nil = bidx[(size_t)b * NB + ltid];
        int   bl  = (nil - 3) * (5 + CNUM);
        int   ixl = (int)(cxl / DIV);
        int   iyl = (int)(cyl / DIV);
        float ax  = (cxl - (float)ixl * DIV) / DIV;
        float ay  = (cyl - (float)iyl * DIV) / DIV;
        int   keyl = bl * SS + ixl * SDIM + iyl;

        const float* xc = xb + keyl;
        float obj = xc[0 * SS];
        float rax = xc[1 * SS];
        float ray = xc[2 * SS];
        float s3  = xc[3 * SS];
        float s4  = xc[4 * SS];

        float sig3 = 1.0f / (1.0f + __expf(-s3));
        float sig4 = 1.0f / (1.0f + __expf(-s4));
        float rw = c_anchor[nil][0] * __expf(4.0f * sig3 - 2.0f);
        float rh = c_anchor[nil][1] * __expf(4.0f * sig4 - 2.0f);

        // IoU
        float b1x1 = rax * DIV - rw * 0.5f, b1y1 = ray * DIV - rh * 0.5f;
        float b1x2 = rax * DIV + rw * 0.5f, b1y2 = ray * DIV + rh * 0.5f;
        float b2x1 = ax * DIV - w * 0.5f,   b2y1 = ay * DIV - h * 0.5f;
        float b2x2 = ax * DIV + w * 0.5f,   b2y2 = ay * DIV + h * 0.5f;
        float A  = (b1x2 - b1x1 + 1.0f) * (b1y2 - b1y1 + 1.0f);
        float Bt = (b2x2 - b2x1 + 1.0f) * (b2y2 - b2y1 + 1.0f);
        float CM = (fminf(b1x2, b2x2) - fmaxf(b1x1, b2x1) + 1.0f) *
                   (fminf(b1y2, b2y2) - fmaxf(b1y1, b2y1) + 1.0f);
        float r  = CM / (A + Bt - CM);
        float iou = (r < 0.0f) ? 0.0f : r;

        float d0 = obj - iou;
        float d1 = rax - ax;
        float d2 = ray - ay;
        float d3 = (rw - w) / IMG;
        float d4 = (rh - h) / IMG;
        float boxloss = d0 * d0 + d1 * d1 + d2 * d2 + d3 * d3 + d4 * d4;

        // dedup: unique if this lane is the lowest lane with this key
        unsigned int peers = __match_any_sync(0xffffffffu, keyl);
        bool uniq = ((int)(__ffs(peers)) - 1 == ltid);
        float corr = uniq ? obj * obj : 0.0f;   // xb[key] == obj
        float ucnt = uniq ? 1.0f : 0.0f;

        boxloss = warp_sum(boxloss);
        corr    = warp_sum(corr);
        ucnt    = warp_sum(ucnt);
        if (ltid == 0) {
            sh_scalar[half][0] = boxloss;
            sh_scalar[half][1] = corr;
            sh_scalar[half][2] = ucnt;
        }
    }

    // ================= per-thread accumulation (no sync needed yet) =========
    const int cls_t = (int)cls;
    float lsum = 0.0f;
#pragma unroll
    for (int k = 0; k < 5; ++k) {
        int j = jbase + (k << 4);
        float hot = (j == cls_t) ? 1.0f : 0.0f;
        float d = lab[k] - hot;
        lsum += d * d;
    }
    float nsum = nv.x * nv.x + nv.y * nv.y + nv.z * nv.z + nv.w * nv.w;

    // ================= per-half block reduce (16 warps/half) ================
    lsum = warp_sum(lsum);
    nsum = warp_sum(nsum);
    int lwid = ltid >> 5;
    if ((ltid & 31) == 0) { sh_wl[half][lwid] = lsum; sh_wn[half][lwid] = nsum; }
    __syncthreads();

    if (ltid == 0) {
        float lt = 0.0f, nt = 0.0f;
#pragma unroll
        for (int i = 0; i < 16; ++i) { lt += sh_wl[half][i]; nt += sh_wn[half][i]; }
        float cnt   = 3.0f * (float)SS - sh_scalar[half][2];
        float noobj = (nt - sh_scalar[half][1]) / cnt;
        sh_loss[half] = (5.0f / (float)NB) * sh_scalar[half][0]
                      + lt / (float)(NB * CNUM)
                      + 0.5f * noobj;
    }
    __syncthreads();

    if (tid == 0) {
        g_partial[blockIdx.x] = sh_loss[0] + sh_loss[1];
        __threadfence();   // release g_partial before taking the ticket
        unsigned int ticket = atomicAdd(&g_count, 1u);
        sh_islast = (ticket == NCTA - 1) ? 1 : 0;
    }
    __syncthreads();

    // ---- last CTA: deterministic final reduction over 128 partials ----
    if (sh_islast) {
        if (tid < NCTA) {
            __threadfence();   // acquire side
            float v = g_partial[tid];
            v = warp_sum(v);
            if ((tid & 31) == 0) sh_wl[0][tid >> 5] = v;
        }
        __syncthreads();
        if (tid == 0) {
            float t2 = 0.0f;
#pragma unroll
            for (int i = 0; i < NCTA / 32; ++i) t2 += sh_wl[0][i];
            out[0] = t2;
            g_count = 0;   // reset for next graph replay
        }
    }
}

extern "C" void kernel_launch(void* const* d_in, const int* in_sizes, int n_in,
                              void* d_out, int out_size)
{
    const float* x    = (const float*)d_in[0];
    const float* box  = (const float*)d_in[1];
    const int*   bidx = (const int*)d_in[2];
    yolo_fused_kernel<<<NCTA, 1024>>>(x, box, bidx, (float*)d_out);
}

// round 17
// speedup vs baseline: 1.1866x; 1.1866x over previous
#include <cuda_runtime.h>

#define SDIM 26
#define SS   676          // 26*26
#define CNUM 80
#define NCH  255          // 3*(5+80)
#define NB   32
#define BATCH 256
#define IPB  2            // images per block
#define TPI  512          // threads per image
#define NCTA (BATCH / IPB)
#define DIV  16.0f        // 416/26
#define IMG  416.0f

__device__ float g_partial[NCTA];
__device__ unsigned int g_count = 0;

__device__ __constant__ float c_anchor[9][2] = {
    {10.f,13.f},{16.f,30.f},{33.f,23.f},{30.f,61.f},{62.f,45.f},
    {59.f,119.f},{116.f,90.f},{156.f,198.f},{373.f,326.f}};

__device__ __forceinline__ float warp_sum(float v) {
#pragma unroll
    for (int o = 16; o > 0; o >>= 1) v += __shfl_down_sync(0xffffffffu, v, o);
    return v;
}

// L2 evict_last policy (fraction = 1.0): created once, reused by all x loads.
__device__ __forceinline__ unsigned long long mk_sticky_policy() {
    unsigned long long p;
    asm("createpolicy.fractional.L2::evict_last.b64 %0, 1.0;" : "=l"(p));
    return p;
}

// L2-sticky scalar load (read-only path, policy-carried evict_last hint)
__device__ __forceinline__ float ldg_sticky(const float* p, unsigned long long pol) {
    float v;
    asm("ld.global.nc.L2::cache_hint.f32 %0, [%1], %2;"
        : "=f"(v) : "l"(p), "l"(pol));
    return v;
}

// L2-sticky float4 load
__device__ __forceinline__ float4 ldg_sticky4(const float4* p, unsigned long long pol) {
    float4 v;
    asm("ld.global.nc.L2::cache_hint.v4.f32 {%0,%1,%2,%3}, [%4], %5;"
        : "=f"(v.x), "=f"(v.y), "=f"(v.z), "=f"(v.w) : "l"(p), "l"(pol));
    return v;
}

__global__ __launch_bounds__(1024) void yolo_fused_kernel(
    const float* __restrict__ x,      // (B, 255, 26, 26)
    const float* __restrict__ box,    // (B, 32, 5)
    const int*   __restrict__ bidx,   // (B, 32)
    float*       __restrict__ out)
{
    const int tid  = threadIdx.x;
    const int half = tid >> 9;            // which image within the block
    const int ltid = tid & (TPI - 1);     // thread id within the half
    const int b    = blockIdx.x * IPB + half;
    const float* xb = x + (size_t)b * NCH * SS;

    const unsigned long long pol = mk_sticky_policy();

    __shared__ float sh_wl[IPB][16];      // per-warp label partials
    __shared__ float sh_wn[IPB][16];      // per-warp noobj partials
    __shared__ float sh_scalar[IPB][3];   // boxloss, corr, ucnt
    __shared__ float sh_loss[IPB];
    __shared__ int   sh_islast;

    // ================= issue ALL independent loads up front =================

    // noobj float4 (507 per image, one predicated load per thread)
    float4 nv = make_float4(0.f, 0.f, 0.f, 0.f);
    if (ltid < 3 * (SS / 4)) {
        int c = ltid / (SS / 4);
        int o = ltid - c * (SS / 4);
        nv = ldg_sticky4(((const float4*)(xb + (size_t)(c * 85) * SS)) + o, pol);
    }

    // per-thread gather address: t = box index (16 threads share), jbase = channel lane
    const int t     = ltid >> 4;
    const int jbase = ltid & 15;
    const float* bp = box + ((size_t)b * NB + t) * 5;
    const float  cls = bp[0];
    const float  cx  = bp[1];
    const float  cy  = bp[2];
    const int    ni  = bidx[(size_t)b * NB + t];     // 3..5
    const int    base = (ni - 3) * (5 + CNUM);       // 0 / 85 / 170
    const int    ix  = (int)(cx / DIV);
    const int    iy  = (int)(cy / DIV);
    const int    key = base * SS + ix * SDIM + iy;
    const int    off = key + 5 * SS;

    // 5 independent label loads, issued before any sync
    float lab[5];
#pragma unroll
    for (int k = 0; k < 5; ++k)
        lab[k] = ldg_sticky(xb + (size_t)(off + (jbase + (k << 4)) * SS), pol);

    // ================= warp 0 / warp 16: per-box scalar path =================
    if (ltid < NB) {
        // this lane owns box 'ltid' (recompute; data is L1-hot)
        const float* bpl = box + ((size_t)b * NB + ltid) * 5;
        float cxl = bpl[1];
        float cyl = bpl[2];
        float w   = bpl[3];
        float h   = bpl[4];
        int   nil = bidx[(size_t)b * NB + ltid];
        int   bl  = (nil - 3) * (5 + CNUM);
        int   ixl = (int)(cxl / DIV);
        int   iyl = (int)(cyl / DIV);
        float ax  = (cxl - (float)ixl * DIV) / DIV;
        float ay  = (cyl - (float)iyl * DIV) / DIV;
        int   keyl = bl * SS + ixl * SDIM + iyl;

        const float* xc = xb + keyl;
        float obj = ldg_sticky(xc + 0 * SS, pol);
        float rax = ldg_sticky(xc + 1 * SS, pol);
        float ray = ldg_sticky(xc + 2 * SS, pol);
        float s3  = ldg_sticky(xc + 3 * SS, pol);
        float s4  = ldg_sticky(xc + 4 * SS, pol);

        float sig3 = 1.0f / (1.0f + __expf(-s3));
        float sig4 = 1.0f / (1.0f + __expf(-s4));
        float rw = c_anchor[nil][0] * __expf(4.0f * sig3 - 2.0f);
        float rh = c_anchor[nil][1] * __expf(4.0f * sig4 - 2.0f);

        // IoU
        float b1x1 = rax * DIV - rw * 0.5f, b1y1 = ray * DIV - rh * 0.5f;
        float b1x2 = rax * DIV + rw * 0.5f, b1y2 = ray * DIV + rh * 0.5f;
        float b2x1 = ax * DIV - w * 0.5f,   b2y1 = ay * DIV - h * 0.5f;
        float b2x2 = ax * DIV + w * 0.5f,   b2y2 = ay * DIV + h * 0.5f;
        float A  = (b1x2 - b1x1 + 1.0f) * (b1y2 - b1y1 + 1.0f);
        float Bt = (b2x2 - b2x1 + 1.0f) * (b2y2 - b2y1 + 1.0f);
        float CM = (fminf(b1x2, b2x2) - fmaxf(b1x1, b2x1) + 1.0f) *
                   (fminf(b1y2, b2y2) - fmaxf(b1y1, b2y1) + 1.0f);
        float r  = CM / (A + Bt - CM);
        float iou = (r < 0.0f) ? 0.0f : r;

        float d0 = obj - iou;
        float d1 = rax - ax;
        float d2 = ray - ay;
        float d3 = (rw - w) / IMG;
        float d4 = (rh - h) / IMG;
        float boxloss = d0 * d0 + d1 * d1 + d2 * d2 + d3 * d3 + d4 * d4;

        // dedup: unique if this lane is the lowest lane with this key
        unsigned int peers = __match_any_sync(0xffffffffu, keyl);
        bool uniq = ((int)(__ffs(peers)) - 1 == ltid);
        float corr = uniq ? obj * obj : 0.0f;   // xb[key] == obj
        float ucnt = uniq ? 1.0f : 0.0f;

        boxloss = warp_sum(boxloss);
        corr    = warp_sum(corr);
        ucnt    = warp_sum(ucnt);
        if (ltid == 0) {
            sh_scalar[half][0] = boxloss;
            sh_scalar[half][1] = corr;
            sh_scalar[half][2] = ucnt;
        }
    }

    // ================= per-thread accumulation (no sync needed yet) =========
    const int cls_t = (int)cls;
    float lsum = 0.0f;
#pragma unroll
    for (int k = 0; k < 5; ++k) {
        int j = jbase + (k << 4);
        float hot = (j == cls_t) ? 1.0f : 0.0f;
        float d = lab[k] - hot;
        lsum += d * d;
    }
    float nsum = nv.x * nv.x + nv.y * nv.y + nv.z * nv.z + nv.w * nv.w;

    // ================= per-half block reduce (16 warps/half) ================
    lsum = warp_sum(lsum);
    nsum = warp_sum(nsum);
    int lwid = ltid >> 5;
    if ((ltid & 31) == 0) { sh_wl[half][lwid] = lsum; sh_wn[half][lwid] = nsum; }
    __syncthreads();

    if (ltid == 0) {
        float lt = 0.0f, nt = 0.0f;
#pragma unroll
        for (int i = 0; i < 16; ++i) { lt += sh_wl[half][i]; nt += sh_wn[half][i]; }
        float cnt   = 3.0f * (float)SS - sh_scalar[half][2];
        float noobj = (nt - sh_scalar[half][1]) / cnt;
        sh_loss[half] = (5.0f / (float)NB) * sh_scalar[half][0]
                      + lt / (float)(NB * CNUM)
                      + 0.5f * noobj;
    }
    __syncthreads();

    if (tid == 0) {
        g_partial[blockIdx.x] = sh_loss[0] + sh_loss[1];
        __threadfence();   // release g_partial before taking the ticket
        unsigned int ticket = atomicAdd(&g_count, 1u);
        sh_islast = (ticket == NCTA - 1) ? 1 : 0;
    }
    __syncthreads();

    // ---- last CTA: deterministic final reduction over 128 partials ----
    if (sh_islast) {
        if (tid < NCTA) {
            __threadfence();   // acquire side
            float v = g_partial[tid];
            v = warp_sum(v);
            if ((tid & 31) == 0) sh_wl[0][tid >> 5] = v;
        }
        __syncthreads();
        if (tid == 0) {
            float t2 = 0.0f;
#pragma unroll
            for (int i = 0; i < NCTA / 32; ++i) t2 += sh_wl[0][i];
            out[0] = t2;
            g_count = 0;   // reset for next graph replay
        }
    }
}

extern "C" void kernel_launch(void* const* d_in, const int* in_sizes, int n_in,
                              void* d_out, int out_size)
{
    const float* x    = (const float*)d_in[0];
    const float* box  = (const float*)d_in[1];
    const int*   bidx = (const int*)d_in[2];
    yolo_fused_kernel<<<NCTA, 1024>>>(x, box, bidx, (float*)d_out);
}